// round 1
// baseline (speedup 1.0000x reference)
#include <cuda_runtime.h>

// ---------------- geometry ----------------
#define TX 32
#define TY 8
#define TZ 8
#define HX 36            // TX + 4
#define HY 12            // TY + 4
#define HZ 12            // TZ + 4
#define HXB 37           // bufB row padded to 37 floats -> conflict-free x-pass

#define A_STRIDE (HY*HX)          // 432 floats per z-plane
#define A_Q      (TZ*HY*HX)       // 3456 floats per quantity
#define A_ELEMS  (5*A_Q)          // 17280
#define B_Q      (TZ*TY*HXB)      // 2368
#define B_ELEMS  (5*B_Q)          // 11840
#define XY_ELEMS (HZ*HY*HX)       // 5184
#define SMEM_FLOATS (A_ELEMS + B_ELEMS)   // 29120
#define SMEM_BYTES  (SMEM_FLOATS * 4)     // 116480

// 1-D separable Gaussian weights (sigma=1.5, window=5), normalized.
// Literals so ptxas emits FFMA R,R,IMM,R (double-rate imm form).
#define G0 0.1200784f
#define G1 0.2338808f
#define G2 0.2920817f

#define C1 1.0e-4f       // 0.01^2
#define C2 9.0e-4f       // 0.03^2

#define NBLOCKS 8192     // 4 * 16 * 128

__device__ float g_partials[NBLOCKS];

// symmetric 5-tap conv
#define CONV5(v, o) (G2*(v)[(o)+2] + G1*((v)[(o)+1] + (v)[(o)+3]) + G0*((v)[(o)] + (v)[(o)+4]))

__global__ void __launch_bounds__(256, 2)
ssim_main(const float* __restrict__ X, const float* __restrict__ Y)
{
    extern __shared__ float sm[];
    float* bufA = sm;                 // [5][TZ][HY][HX]
    float* reg2 = sm + A_ELEMS;       // union region (11840 floats)
    float* sx   = reg2;               // [HZ][HY][HX] during load/z-pass
    float* sy   = reg2 + XY_ELEMS;
    float* bufB = reg2;               // [5][TZ][TY][HXB] after z-pass

    const int tid = threadIdx.x;
    const int nc  = blockIdx.z >> 4;          // 0..7  (n*4+c)
    const int z0  = (blockIdx.z & 15) * TZ;   // d tile
    const int y0  = blockIdx.y * TY;          // h tile
    const int x0  = blockIdx.x * TX;          // w tile
    const long long base = (long long)nc * (128LL*128*128);

    // ---------------- load x,y tiles with halo, apply (v+1)*0.5, zero-pad ----
    for (int i = tid; i < XY_ELEMS; i += 256) {
        int w = i % HX;
        int t = i / HX;
        int h = t % HY;
        int z = t / HY;
        int gz = z0 + z - 2, gh = y0 + h - 2, gw = x0 + w - 2;
        float vx = 0.f, vy = 0.f;
        if ((unsigned)gz < 128u && (unsigned)gh < 128u && (unsigned)gw < 128u) {
            long long gi = base + (((long long)gz * 128 + gh) * 128 + gw);
            vx = (X[gi] + 1.f) * 0.5f;
            vy = (Y[gi] + 1.f) * 0.5f;
        }
        sx[i] = vx;
        sy[i] = vy;
    }
    __syncthreads();

    // ---------------- z-pass: form 5 channels on the fly, conv along z ------
    for (int col = tid; col < HY*HX; col += 256) {
        float a[HZ], b[HZ], aa[HZ], bb[HZ], ab[HZ];
        #pragma unroll
        for (int z = 0; z < HZ; z++) {
            float av = sx[z*A_STRIDE + col];
            float bv = sy[z*A_STRIDE + col];
            a[z] = av; b[z] = bv;
            aa[z] = av*av; bb[z] = bv*bv; ab[z] = av*bv;
        }
        #pragma unroll
        for (int oz = 0; oz < TZ; oz++) {
            int o = oz*A_STRIDE + col;
            bufA[0*A_Q + o] = CONV5(a,  oz);
            bufA[1*A_Q + o] = CONV5(b,  oz);
            bufA[2*A_Q + o] = CONV5(aa, oz);
            bufA[3*A_Q + o] = CONV5(bb, oz);
            bufA[4*A_Q + o] = CONV5(ab, oz);
        }
    }
    __syncthreads();   // bufA ready; sx/sy dead -> region reused as bufB

    // ---------------- y-pass: conv along h, bufA -> bufB --------------------
    for (int col = tid; col < TZ*HX; col += 256) {
        int w = col % HX;
        int z = col / HX;
        const float* pa = bufA + z*A_STRIDE + w;
        float v0[HY], v1[HY], v2[HY], v3[HY], v4[HY];
        #pragma unroll
        for (int h = 0; h < HY; h++) {
            int off = h*HX;
            v0[h] = pa[0*A_Q + off];
            v1[h] = pa[1*A_Q + off];
            v2[h] = pa[2*A_Q + off];
            v3[h] = pa[3*A_Q + off];
            v4[h] = pa[4*A_Q + off];
        }
        float* pb = bufB + (z*TY)*HXB + w;
        #pragma unroll
        for (int oy = 0; oy < TY; oy++) {
            int off = oy*HXB;
            pb[0*B_Q + off] = CONV5(v0, oy);
            pb[1*B_Q + off] = CONV5(v1, oy);
            pb[2*B_Q + off] = CONV5(v2, oy);
            pb[3*B_Q + off] = CONV5(v3, oy);
            pb[4*B_Q + off] = CONV5(v4, oy);
        }
    }
    __syncthreads();

    // ---------------- x-pass + SSIM + partial reduction ---------------------
    float lsum = 0.f;
    {
        // 256 threads == 8z * 8h * 4 segments of 8 outputs
        int seg = tid & 3;
        int row = tid >> 2;      // 0..63
        int h   = row & 7;
        int z   = row >> 3;
        const float* pb = bufB + (z*TY + h)*HXB + seg*8;
        float u0[12], u1[12], u2[12], u3[12], u4[12];
        #pragma unroll
        for (int j = 0; j < 12; j++) {
            u0[j] = pb[0*B_Q + j];
            u1[j] = pb[1*B_Q + j];
            u2[j] = pb[2*B_Q + j];
            u3[j] = pb[3*B_Q + j];
            u4[j] = pb[4*B_Q + j];
        }
        #pragma unroll
        for (int ow = 0; ow < 8; ow++) {
            float mu1 = CONV5(u0, ow);
            float mu2 = CONV5(u1, ow);
            float ex2 = CONV5(u2, ow);
            float ey2 = CONV5(u3, ow);
            float exy = CONV5(u4, ow);
            float mu1s = mu1*mu1, mu2s = mu2*mu2, mu12 = mu1*mu2;
            float s1  = ex2 - mu1s;
            float s2  = ey2 - mu2s;
            float s12 = exy - mu12;
            float num = (2.f*mu12 + C1) * (2.f*s12 + C2);
            float den = (mu1s + mu2s + C1) * (s1 + s2 + C2);
            lsum += num / den;
        }
    }

    // warp reduce
    #pragma unroll
    for (int o = 16; o; o >>= 1)
        lsum += __shfl_xor_sync(0xffffffffu, lsum, o);

    __syncthreads();             // all bufB reads complete before smem reuse
    if ((tid & 31) == 0) sm[tid >> 5] = lsum;
    __syncthreads();
    if (tid == 0) {
        float s = 0.f;
        #pragma unroll
        for (int i = 0; i < 8; i++) s += sm[i];
        int bid = (blockIdx.z * gridDim.y + blockIdx.y) * gridDim.x + blockIdx.x;
        g_partials[bid] = s;
    }
}

__global__ void ssim_reduce(float* __restrict__ out)
{
    __shared__ double sd[256];
    double s = 0.0;
    for (int i = threadIdx.x; i < NBLOCKS; i += 256)
        s += (double)g_partials[i];
    sd[threadIdx.x] = s;
    __syncthreads();
    #pragma unroll
    for (int st = 128; st; st >>= 1) {
        if (threadIdx.x < st) sd[threadIdx.x] += sd[threadIdx.x + st];
        __syncthreads();
    }
    if (threadIdx.x == 0)
        out[0] = (float)(sd[0] * (1.0 / 16777216.0));
}

extern "C" void kernel_launch(void* const* d_in, const int* in_sizes, int n_in,
                              void* d_out, int out_size)
{
    const float* X = (const float*)d_in[0];
    const float* Y = (const float*)d_in[1];
    // d_in[2] is the Gaussian kernel; weights are baked in as literals.

    cudaFuncSetAttribute(ssim_main, cudaFuncAttributeMaxDynamicSharedMemorySize, SMEM_BYTES);

    dim3 grid(4, 16, 128);       // 4 w-tiles, 16 h-tiles, 16 d-tiles * 8 (n*c)
    ssim_main<<<grid, 256, SMEM_BYTES>>>(X, Y);
    ssim_reduce<<<1, 256>>>((float*)d_out);
}

// round 2
// speedup vs baseline: 1.6214x; 1.6214x over previous
#include <cuda_runtime.h>

// ---------------- geometry ----------------
#define TX 32
#define TY 8
#define HXP 36            // TX + 4 (x halo)
#define HYP 12            // TY + 4 (y halo)
#define ZCHUNK 64         // z outputs per block
#define NBLOCKS 1024      // 4 x-tiles * 16 y-tiles * (8 nc * 2 z-chunks)

// 1-D separable Gaussian (sigma=1.5, window=5), normalized; baked as literals.
#define G0 0.12007838f
#define G1 0.23388076f
#define G2 0.29208171f

#define C1f 1.0e-4f       // 0.01^2
#define C2f 9.0e-4f       // 0.03^2

__device__ float g_partials[NBLOCKS];

__global__ void __launch_bounds__(256, 4)
ssim_main(const float* __restrict__ X, const float* __restrict__ Y)
{
    __shared__ float sx[HYP * HXP];          // 432 floats: raw x plane (scaled)
    __shared__ float sy[HYP * HXP];          // 432 floats: raw y plane (scaled)
    __shared__ float ych[5][TY * HXP];       // 1440 floats: y-convolved channels

    const int tid = threadIdx.x;
    const int nc  = blockIdx.z >> 1;                 // 0..7 (n*4 + c)
    const int zb  = (blockIdx.z & 1) * ZCHUNK;       // 0 or 64
    const int y0  = blockIdx.y * TY;
    const int x0  = blockIdx.x * TX;
    const float* Xb = X + (size_t)nc * (128 * 128 * 128);
    const float* Yb = Y + (size_t)nc * (128 * 128 * 128);

    const int ox    = tid & 31;
    const int oy    = tid >> 5;
    const int xbase = oy * HXP + ox;

    // z-conv accumulators: 5 channels x 5 in-flight output planes (slots)
    float a0[5], a1[5], a2[5], a3[5], a4[5];
    #pragma unroll
    for (int i = 0; i < 5; i++) { a0[i] = a1[i] = a2[i] = a3[i] = a4[i] = 0.f; }

    float lsum = 0.f;
    const float GW[5] = {G0, G1, G2, G1, G0};

    // iterate planes zp = zb-2 + it, it = 0..69 (68 needed, 2 padding)
    for (int grp = 0; grp < 14; ++grp) {
        #pragma unroll
        for (int s = 0; s < 5; ++s) {
            const int it = grp * 5 + s;
            const int zp = zb - 2 + it;

            // ---- load plane (x,y) with halo, scale (v+1)*0.5, zero-pad OOB ----
            for (int i = tid; i < HYP * HXP; i += 256) {
                int w = i % HXP, h = i / HXP;
                int gw = x0 + w - 2, gh = y0 + h - 2;
                float vx = 0.f, vy = 0.f;
                if ((unsigned)zp < 128u && (unsigned)gh < 128u && (unsigned)gw < 128u) {
                    int gi = (zp * 128 + gh) * 128 + gw;
                    vx = fmaf(Xb[gi], 0.5f, 0.5f);
                    vy = fmaf(Yb[gi], 0.5f, 0.5f);
                }
                sx[i] = vx;
                sy[i] = vy;
            }
            __syncthreads();

            // ---- y-pass: form 5 channels on the fly, conv along y ----
            for (int j = tid; j < TY * HXP; j += 256) {
                int w = j % HXP, yy = j / HXP;
                float s0 = 0.f, s1 = 0.f, s2 = 0.f, s3 = 0.f, s4 = 0.f;
                #pragma unroll
                for (int t = 0; t < 5; ++t) {
                    float g = GW[t];
                    float a = sx[(yy + t) * HXP + w];
                    float b = sy[(yy + t) * HXP + w];
                    float ga = g * a, gb = g * b;
                    s0 += ga;
                    s1 += gb;
                    s2 = fmaf(ga, a, s2);
                    s3 = fmaf(gb, b, s3);
                    s4 = fmaf(ga, b, s4);
                }
                ych[0][j] = s0; ych[1][j] = s1; ych[2][j] = s2;
                ych[3][j] = s3; ych[4][j] = s4;
            }
            __syncthreads();

            // ---- x-pass: 5-tap conv along x, per-thread output column ----
            #define XC(c) (G2 * ych[c][xbase + 2] \
                         + G1 * (ych[c][xbase + 1] + ych[c][xbase + 3]) \
                         + G0 * (ych[c][xbase] + ych[c][xbase + 4]))
            float v0 = XC(0), v1 = XC(1), v2 = XC(2), v3 = XC(3), v4 = XC(4);
            #undef XC

            // ---- z accumulation: contribution k completes at iteration it+k ----
            #pragma unroll
            for (int k = 0; k < 5; ++k) {
                const int sl = (s + k) % 5;          // static after unroll
                float g = GW[k];
                a0[sl] = fmaf(g, v0, a0[sl]);
                a1[sl] = fmaf(g, v1, a1[sl]);
                a2[sl] = fmaf(g, v2, a2[sl]);
                a3[sl] = fmaf(g, v3, a3[sl]);
                a4[sl] = fmaf(g, v4, a4[sl]);
            }

            // ---- slot s is complete: output plane oz = zb - 4 + it ----
            if (it >= 4 && it < 68) {
                float mu1 = a0[s], mu2 = a1[s];
                float mu1s = mu1 * mu1, mu2s = mu2 * mu2, mu12 = mu1 * mu2;
                float sg1  = a2[s] - mu1s;
                float sg2  = a3[s] - mu2s;
                float sg12 = a4[s] - mu12;
                float num = (2.f * mu12 + C1f) * (2.f * sg12 + C2f);
                float den = (mu1s + mu2s + C1f) * (sg1 + sg2 + C2f);
                lsum += __fdividef(num, den);
            }
            a0[s] = 0.f; a1[s] = 0.f; a2[s] = 0.f; a3[s] = 0.f; a4[s] = 0.f;
        }
    }

    // ---- block reduction ----
    #pragma unroll
    for (int o = 16; o; o >>= 1)
        lsum += __shfl_xor_sync(0xffffffffu, lsum, o);
    __syncthreads();                       // sx reuse as scratch
    if ((tid & 31) == 0) sx[tid >> 5] = lsum;
    __syncthreads();
    if (tid == 0) {
        float t = 0.f;
        #pragma unroll
        for (int i = 0; i < 8; i++) t += sx[i];
        g_partials[(blockIdx.z * 16 + blockIdx.y) * 4 + blockIdx.x] = t;
    }
}

__global__ void ssim_reduce(float* __restrict__ out)
{
    __shared__ double sd[256];
    double s = 0.0;
    for (int i = threadIdx.x; i < NBLOCKS; i += 256)
        s += (double)g_partials[i];
    sd[threadIdx.x] = s;
    __syncthreads();
    #pragma unroll
    for (int st = 128; st; st >>= 1) {
        if (threadIdx.x < st) sd[threadIdx.x] += sd[threadIdx.x + st];
        __syncthreads();
    }
    if (threadIdx.x == 0)
        out[0] = (float)(sd[0] * (1.0 / 16777216.0));
}

extern "C" void kernel_launch(void* const* d_in, const int* in_sizes, int n_in,
                              void* d_out, int out_size)
{
    const float* X = (const float*)d_in[0];
    const float* Y = (const float*)d_in[1];
    // d_in[2] is the Gaussian kernel; weights are baked in as literals.

    dim3 grid(4, 16, 16);    // x-tiles, y-tiles, nc*2 z-chunks
    ssim_main<<<grid, 256>>>(X, Y);
    ssim_reduce<<<1, 256>>>((float*)d_out);
}